// round 13
// baseline (speedup 1.0000x reference)
#include <cuda_runtime.h>
#include <cstdint>

// StructureTensorEffect, B=4, C=3, H=W=1024.
// Separable: s_u = Gx*Sy, s_v = Sx*Gy, per-batch-constant stencils.
// sigma in [0.5,2.5) => JP = floor(sigma) in {0,1,2}; templated on JP.
//
// R13: tall tile (256x32) with double-buffered 4-row chunk pipeline.
// Phase-1 (198 threads = 66 strips x 3 ch) carries a rolling vertical window
// in registers across all 32 rows (1 fresh LDG.128/row). Each iteration:
// issue next chunk's LDGs -> consume current chunk (packed quadratics,
// R10 recipe) -> integrate loads + STS -> sync. f32x2 packed math throughout.

#define Wd 1024
#define Hd 1024
#define HW (Hd*Wd)
#define TX 256
#define TY 32
#define CHR 4                      // rows per chunk
#define NCHK (TY/CHR)              // 8
#define HX 4
#define SW (TX + 2*HX)             // 264 floats per smem row
#define NTH 256
#define NSTRIP (SW/4)              // 66
#define PTASK (NSTRIP*3)           // 198 phase-1 tasks
#define SMEM_FLOATS (2*3*CHR*SW)   // per array: 6336
#define SMEM_BYTES (2*SMEM_FLOATS*4)   // 50688

// ---- f32x2 packed helpers ----
__device__ __forceinline__ uint64_t pk(float lo, float hi) {
    uint64_t r;
    asm("mov.b64 %0, {%1, %2};" : "=l"(r)
        : "r"(__float_as_uint(lo)), "r"(__float_as_uint(hi)));
    return r;
}
__device__ __forceinline__ void upk(uint64_t v, float& lo, float& hi) {
    uint32_t a, b;
    asm("mov.b64 {%0, %1}, %2;" : "=r"(a), "=r"(b) : "l"(v));
    lo = __uint_as_float(a); hi = __uint_as_float(b);
}
__device__ __forceinline__ uint64_t mul2(uint64_t a, uint64_t b) {
    uint64_t r; asm("mul.rn.f32x2 %0, %1, %2;" : "=l"(r) : "l"(a), "l"(b)); return r;
}
__device__ __forceinline__ uint64_t add2(uint64_t a, uint64_t b) {
    uint64_t r; asm("add.rn.f32x2 %0, %1, %2;" : "=l"(r) : "l"(a), "l"(b)); return r;
}
__device__ __forceinline__ uint64_t fma2(uint64_t a, uint64_t b, uint64_t c) {
    uint64_t r; asm("fma.rn.f32x2 %0, %1, %2, %3;" : "=l"(r) : "l"(a), "l"(b), "l"(c)); return r;
}
#define NEG1_2 0xBF800000BF800000ULL
#define C100_2 0x42C8000042C80000ULL

__device__ __forceinline__ int clampi(int v, int lo, int hi) {
    return min(max(v, lo), hi);
}

// Exact per-pixel path replicating reference clip semantics (left/top only).
__device__ __noinline__ void exact_pixel(const float* __restrict__ xb, float s,
                                         int gx, int gy,
                                         float& A, float& Bv, float& Cv) {
    const float OU[8] = {-1.f,-1.f,-1.f, 0.f, 0.f, 1.f, 1.f, 1.f};
    const float OV[8] = {-1.f, 0.f, 1.f,-1.f, 1.f,-1.f, 0.f, 1.f};
    const float KU[8] = {-0.25f,-0.5f,-0.25f, 0.f, 0.f, 0.25f, 0.5f, 0.25f};
    const float KV[8] = {-0.25f, 0.f, 0.25f,-0.5f, 0.5f,-0.25f, 0.f, 0.25f};
    float su[3] = {0.f,0.f,0.f}, sv[3] = {0.f,0.f,0.f};
    #pragma unroll
    for (int t = 0; t < 8; ++t) {
        float px = (float)gx + OU[t] * s;
        float py = (float)gy + OV[t] * s;
        float x0f = floorf(px), y0f = floorf(py);
        float fx = px - x0f, fy = py - y0f;
        int x0 = clampi((int)x0f, 0, Wd - 1);
        int x1 = min(x0 + 1, Wd - 1);
        int y0 = clampi((int)y0f, 0, Hd - 1);
        int y1 = min(y0 + 1, Hd - 1);
        float w00 = (1.f - fx) * (1.f - fy);
        float w01 = fx * (1.f - fy);
        float w10 = (1.f - fx) * fy;
        float w11 = fx * fy;
        #pragma unroll
        for (int c = 0; c < 3; ++c) {
            const float* p = xb + c * HW;
            float bil = w00 * __ldg(&p[y0 * Wd + x0]) + w01 * __ldg(&p[y0 * Wd + x1])
                      + w10 * __ldg(&p[y1 * Wd + x0]) + w11 * __ldg(&p[y1 * Wd + x1]);
            su[c] += KU[t] * bil;
            sv[c] += KV[t] * bil;
        }
    }
    A = 0.f; Bv = 0.f; Cv = 0.f;
    #pragma unroll
    for (int c = 0; c < 3; ++c) {
        float l = (c == 0) ? 100.f : 1.f;
        float a = su[c] * l, b = sv[c] * l;
        A += a * a; Bv += b * b; Cv += a * b;
    }
}

struct P2 { uint64_t lo, hi; };

template<int JP>
__device__ __forceinline__ void run_tile(const float* __restrict__ xb, float s,
                                         float* __restrict__ smS,
                                         float* __restrict__ smG,
                                         float* __restrict__ out,
                                         int b, int bx0, int by0, int tid) {
    constexpr int WIN = 2 * JP + 3;
    const float fp  = s - (float)JP;
    const float wp0 = 0.5f * (1.f - fp);
    const float wp1 = 0.5f * fp;
    const float wm0 = wp1;
    const float wm1 = wp0;
    const uint64_t Wm0 = pk(wm0, wm0), Wm1 = pk(wm1, wm1);
    const uint64_t Wp0 = pk(wp0, wp0), Wp1 = pk(wp1, wp1);

    // ---- phase-1 setup ----
    const bool pact = (tid < PTASK);
    int ch = 0, strip = 0;
    const float* plane = xb;
    int gxu = 0; bool edge = false;
    int cx0 = 0, cx1 = 0, cx2 = 0, cx3 = 0;
    if (pact) {
        ch    = tid / NSTRIP;
        strip = tid - ch * NSTRIP;
        plane = xb + ch * HW;
        gxu   = bx0 - HX + strip * 4;
        edge  = (gxu < 0) || (gxu > Wd - 4);
        cx0 = clampi(gxu + 0, 0, Wd - 1);
        cx1 = clampi(gxu + 1, 0, Wd - 1);
        cx2 = clampi(gxu + 2, 0, Wd - 1);
        cx3 = clampi(gxu + 3, 0, Wd - 1);
    }

    auto ldrow4 = [&](int ty) -> float4 {   // ty = tile-relative row
        const int yo = clampi(by0 + ty, 0, Hd - 1) * Wd;
        float4 v;
        if (!edge) {
            v = __ldg((const float4*)(plane + yo + gxu));
        } else {
            v.x = __ldg(plane + yo + cx0);
            v.y = __ldg(plane + yo + cx1);
            v.z = __ldg(plane + yo + cx2);
            v.w = __ldg(plane + yo + cx3);
        }
        return v;
    };

    // rolling window: row r lives at slot (r + JP + 1) % WIN
    P2 win[WIN];
    if (pact) {
        #pragma unroll
        for (int r = -JP - 1; r <= JP; ++r) {
            float4 v = ldrow4(r);
            win[r + JP + 1].lo = pk(v.x, v.y);
            win[r + JP + 1].hi = pk(v.z, v.w);
        }
    }

    // produce rows y0..y0+3 into buffer `buf` from pre-loaded `fresh`
    auto produce = [&](int y0, int buf, const float4* fresh) {
        float* sSb = smS + ((buf * 3 + ch) * CHR) * SW + strip * 4;
        float* sGb = smG + ((buf * 3 + ch) * CHR) * SW + strip * 4;
        #pragma unroll
        for (int j = 0; j < CHR; ++j) {
            const int y = y0 + j;
            P2 nw; nw.lo = pk(fresh[j].x, fresh[j].y); nw.hi = pk(fresh[j].z, fresh[j].w);
            win[(y + WIN - 1) % WIN] = nw;
            P2 m0 = win[(y)              % WIN];
            P2 m1 = win[(y + 1)          % WIN];
            P2 ce = win[(y + JP + 1)     % WIN];
            P2 p0 = win[(y + 2 * JP + 1) % WIN];
            P2 p1 = win[(y + 2 * JP + 2) % WIN];
            uint64_t mpl = fma2(Wm1, m1.lo, mul2(Wm0, m0.lo));
            uint64_t mph = fma2(Wm1, m1.hi, mul2(Wm0, m0.hi));
            uint64_t ppl = fma2(Wp1, p1.lo, mul2(Wp0, p0.lo));
            uint64_t pph = fma2(Wp1, p1.hi, mul2(Wp0, p0.hi));
            uint64_t vsl = add2(ce.lo, add2(mpl, ppl));
            uint64_t vsh = add2(ce.hi, add2(mph, pph));
            uint64_t vgl = fma2(mpl, NEG1_2, ppl);
            uint64_t vgh = fma2(mph, NEG1_2, pph);
            *(ulonglong2*)(sSb + j * SW) = make_ulonglong2(vsl, vsh);
            *(ulonglong2*)(sGb + j * SW) = make_ulonglong2(vgl, vgh);
        }
    };

    // ---- phase-2 setup ----
    const int cg   = tid & 63;      // 64 col groups of 4 px
    const int prow = tid >> 6;      // 0..3 row within chunk
    const int xl   = cg * 4;
    const int gxg  = bx0 + xl;
    float* out0 = out + (b * 3 + 0) * HW;
    float* out1 = out + (b * 3 + 1) * HW;
    float* out2 = out + (b * 3 + 2) * HW;
    constexpr int dM = 3 - JP;
    constexpr int dP = 4 + JP;

    auto consume = [&](int k) {
        const int buf = k & 1;
        const int gy  = by0 + k * CHR + prow;
        uint64_t qA[2] = {0, 0}, qB[2] = {0, 0}, qC[2] = {0, 0};
        #pragma unroll
        for (int c = 0; c < 3; ++c) {
            const float* Sp = smS + ((buf * 3 + c) * CHR + prow) * SW + xl;
            const float* Gp = smG + ((buf * 3 + c) * CHR + prow) * SW + xl;
            float4 a0 = *(const float4*)(Sp);
            float4 a1 = *(const float4*)(Sp + 4);
            float4 a2 = *(const float4*)(Sp + 8);
            float4 b0 = *(const float4*)(Gp);
            float4 b1 = *(const float4*)(Gp + 4);
            float4 b2 = *(const float4*)(Gp + 8);
            float sw[12] = {a0.x,a0.y,a0.z,a0.w, a1.x,a1.y,a1.z,a1.w, a2.x,a2.y,a2.z,a2.w};
            float gw[12] = {b0.x,b0.y,b0.z,b0.w, b1.x,b1.y,b1.z,b1.w, b2.x,b2.y,b2.z,b2.w};
            float su[4], sv[4];
            #pragma unroll
            for (int i = 0; i < 4; ++i) {
                su[i] = wp0 * sw[i + dP] + wp1 * sw[i + dP + 1]
                      - wm0 * sw[i + dM] - wm1 * sw[i + dM + 1];
                sv[i] = gw[i + 4]
                      + wm0 * gw[i + dM] + wm1 * gw[i + dM + 1]
                      + wp0 * gw[i + dP] + wp1 * gw[i + dP + 1];
            }
            uint64_t p01 = pk(su[0], su[1]), p23 = pk(su[2], su[3]);
            uint64_t q01 = pk(sv[0], sv[1]), q23 = pk(sv[2], sv[3]);
            if (c == 0) {
                p01 = mul2(p01, C100_2); p23 = mul2(p23, C100_2);
                q01 = mul2(q01, C100_2); q23 = mul2(q23, C100_2);
            }
            qA[0] = fma2(p01, p01, qA[0]);
            qA[1] = fma2(p23, p23, qA[1]);
            qB[0] = fma2(q01, q01, qB[0]);
            qB[1] = fma2(q23, q23, qB[1]);
            qC[0] = fma2(p01, q01, qC[0]);
            qC[1] = fma2(p23, q23, qC[1]);
        }
        const int o = gy * Wd + gxg;
        float A[4], Bv[4], Cv[4];
        upk(qA[0], A[0], A[1]);   upk(qA[1], A[2], A[3]);
        upk(qB[0], Bv[0], Bv[1]); upk(qB[1], Bv[2], Bv[3]);
        upk(qC[0], Cv[0], Cv[1]); upk(qC[1], Cv[2], Cv[3]);
        if (gxg >= 4 && gy > JP) {
            *(float4*)(out0 + o) = make_float4(A[0], A[1], A[2], A[3]);
            *(float4*)(out1 + o) = make_float4(Bv[0], Bv[1], Bv[2], Bv[3]);
            *(float4*)(out2 + o) = make_float4(Cv[0], Cv[1], Cv[2], Cv[3]);
        } else {
            #pragma unroll
            for (int i = 0; i < 4; ++i) {
                int gx = gxg + i;
                float a = A[i], bq = Bv[i], cq = Cv[i];
                if (gx <= JP || gy <= JP) {
                    exact_pixel(xb, s, gx, gy, a, bq, cq);
                }
                out0[o + i] = a;
                out1[o + i] = bq;
                out2[o + i] = cq;
            }
        }
    };

    // ---- pipeline ----
    float4 fresh[CHR];
    if (pact) {
        #pragma unroll
        for (int j = 0; j < CHR; ++j) fresh[j] = ldrow4(j + JP + 1);
        produce(0, 0, fresh);
    }
    __syncthreads();

    #pragma unroll
    for (int k = 0; k < NCHK; ++k) {
        if (k < NCHK - 1 && pact) {
            #pragma unroll
            for (int j = 0; j < CHR; ++j)
                fresh[j] = ldrow4((k + 1) * CHR + j + JP + 1);
        }
        consume(k);
        if (k < NCHK - 1) {
            if (pact) produce((k + 1) * CHR, (k + 1) & 1, fresh);
            __syncthreads();
        }
    }
}

__global__ __launch_bounds__(NTH)
void st13_kernel(const float* __restrict__ x, const float* __restrict__ sigma,
                 float* __restrict__ out) {
    extern __shared__ float sm[];
    float* smS = sm;
    float* smG = sm + SMEM_FLOATS;

    const int b   = blockIdx.z;
    const int bx0 = blockIdx.x * TX;
    const int by0 = blockIdx.y * TY;
    const int tid = threadIdx.x;

    const float s = __ldg(&sigma[b]);
    const int jp = clampi((int)floorf(s), 0, 2);
    const float* xb = x + b * 3 * HW;

    if (jp == 0)      run_tile<0>(xb, s, smS, smG, out, b, bx0, by0, tid);
    else if (jp == 1) run_tile<1>(xb, s, smS, smG, out, b, bx0, by0, tid);
    else              run_tile<2>(xb, s, smS, smG, out, b, bx0, by0, tid);
}

extern "C" void kernel_launch(void* const* d_in, const int* in_sizes, int n_in,
                              void* d_out, int out_size) {
    const float* x     = (const float*)d_in[0];
    const float* sigma = (const float*)d_in[1];
    float* out = (float*)d_out;
    int B = in_sizes[1];

    static_assert(SMEM_BYTES == 50688, "smem size");
    cudaFuncSetAttribute(st13_kernel, cudaFuncAttributeMaxDynamicSharedMemorySize, SMEM_BYTES);

    dim3 grid(Wd / TX, Hd / TY, B);                 // (4, 32, 4) = 512 blocks
    st13_kernel<<<grid, NTH, SMEM_BYTES>>>(x, sigma, out);
}

// round 14
// speedup vs baseline: 1.9659x; 1.9659x over previous
#include <cuda_runtime.h>
#include <cstdint>

// StructureTensorEffect, B=4, C=3, H=W=1024.
// Separable: s_u = Gx*Sy, s_v = Sx*Gy, per-batch-constant stencils.
// sigma in [0.5,2.5) => JP = floor(sigma) in {0,1,2}; templated on JP.
//
// R14 = R10 with (S,G) column-interleaved smem: one 128-bit LDS yields two
// packed (S,G) f32x2 operands, and ONE packed weight (d_k, s_k) per tap
// computes su and sv together: 5 FFMA2/px instead of 9 scalar FMA.
// qAB += acc*acc packed; qC += su*sv scalar from pair halves.
// Stride-2 word pattern made conflict-free by the R5 block-rotation swizzle.

#define Wd 1024
#define Hd 1024
#define TX 128
#define TY 16
#define HX 4
#define SW (TX + 2*HX)            // 136 columns per smem row
#define NTH 256
#define NSTRIP (SW/4)             // 34 strips of 4 columns
#define CHUNK 8
#define NCHUNK (TY/CHUNK)         // 2
#define NVTASK (NSTRIP*NCHUNK*3)  // 204
#define HW (Hd*Wd)
#define ROWF (2*SW)               // floats per interleaved smem row (272)
#define SMEM_FLOATS (3*TY*ROWF)   // 13056
#define SMEM_BYTES (SMEM_FLOATS*4)    // 52224

// ---- f32x2 packed helpers ----
__device__ __forceinline__ uint64_t pk(float lo, float hi) {
    uint64_t r;
    asm("mov.b64 %0, {%1, %2};" : "=l"(r)
        : "r"(__float_as_uint(lo)), "r"(__float_as_uint(hi)));
    return r;
}
__device__ __forceinline__ void upk(uint64_t v, float& lo, float& hi) {
    uint32_t a, b;
    asm("mov.b64 {%0, %1}, %2;" : "=r"(a), "=r"(b) : "l"(v));
    lo = __uint_as_float(a); hi = __uint_as_float(b);
}
__device__ __forceinline__ uint64_t mul2(uint64_t a, uint64_t b) {
    uint64_t r; asm("mul.rn.f32x2 %0, %1, %2;" : "=l"(r) : "l"(a), "l"(b)); return r;
}
__device__ __forceinline__ uint64_t add2(uint64_t a, uint64_t b) {
    uint64_t r; asm("add.rn.f32x2 %0, %1, %2;" : "=l"(r) : "l"(a), "l"(b)); return r;
}
__device__ __forceinline__ uint64_t fma2(uint64_t a, uint64_t b, uint64_t c) {
    uint64_t r; asm("fma.rn.f32x2 %0, %1, %2, %3;" : "=l"(r) : "l"(a), "l"(b), "l"(c)); return r;
}
#define NEG1_2 0xBF800000BF800000ULL
#define C100_2 0x42C8000042C80000ULL

// Rotate odd 128B blocks by one float4 (word) — conflict-free for stride-2
// word accesses and contiguous strip stores (verified R5/R12).
__device__ __forceinline__ int swz(int f) {
    return (f & ~7) | ((f + ((f >> 3) & 1)) & 7);
}

__device__ __forceinline__ int clampi(int v, int lo, int hi) {
    return min(max(v, lo), hi);
}

// Exact per-pixel path replicating reference clip semantics (left/top only).
__device__ __noinline__ void exact_pixel(const float* __restrict__ xb, float s,
                                         int gx, int gy,
                                         float& A, float& Bv, float& Cv) {
    const float OU[8] = {-1.f,-1.f,-1.f, 0.f, 0.f, 1.f, 1.f, 1.f};
    const float OV[8] = {-1.f, 0.f, 1.f,-1.f, 1.f,-1.f, 0.f, 1.f};
    const float KU[8] = {-0.25f,-0.5f,-0.25f, 0.f, 0.f, 0.25f, 0.5f, 0.25f};
    const float KV[8] = {-0.25f, 0.f, 0.25f,-0.5f, 0.5f,-0.25f, 0.f, 0.25f};
    float su[3] = {0.f,0.f,0.f}, sv[3] = {0.f,0.f,0.f};
    #pragma unroll
    for (int t = 0; t < 8; ++t) {
        float px = (float)gx + OU[t] * s;
        float py = (float)gy + OV[t] * s;
        float x0f = floorf(px), y0f = floorf(py);
        float fx = px - x0f, fy = py - y0f;
        int x0 = clampi((int)x0f, 0, Wd - 1);
        int x1 = min(x0 + 1, Wd - 1);
        int y0 = clampi((int)y0f, 0, Hd - 1);
        int y1 = min(y0 + 1, Hd - 1);
        float w00 = (1.f - fx) * (1.f - fy);
        float w01 = fx * (1.f - fy);
        float w10 = (1.f - fx) * fy;
        float w11 = fx * fy;
        #pragma unroll
        for (int c = 0; c < 3; ++c) {
            const float* p = xb + c * HW;
            float bil = w00 * __ldg(&p[y0 * Wd + x0]) + w01 * __ldg(&p[y0 * Wd + x1])
                      + w10 * __ldg(&p[y1 * Wd + x0]) + w11 * __ldg(&p[y1 * Wd + x1]);
            su[c] += KU[t] * bil;
            sv[c] += KV[t] * bil;
        }
    }
    A = 0.f; Bv = 0.f; Cv = 0.f;
    #pragma unroll
    for (int c = 0; c < 3; ++c) {
        float l = (c == 0) ? 100.f : 1.f;
        float a = su[c] * l, b = sv[c] * l;
        A += a * a; Bv += b * b; Cv += a * b;
    }
}

struct P2 { uint64_t lo, hi; };

template<int JP>
__device__ __forceinline__ void run_tile(const float* __restrict__ xb, float s,
                                         float* __restrict__ smI,
                                         float* __restrict__ out,
                                         int b, int bx0, int by0, int tid) {
    const float fp  = s - (float)JP;
    const float wp0 = 0.5f * (1.f - fp);
    const float wp1 = 0.5f * fp;
    const float wm0 = wp1;
    const float wm1 = wp0;

    // ---------------- Phase 1: vertical stencil (f32x2) -> interleaved smem ----
    if (tid < NVTASK) {
        const int c     = tid / (NSTRIP * NCHUNK);
        const int rem   = tid - c * (NSTRIP * NCHUNK);
        const int chunk = rem / NSTRIP;
        const int strip = rem - chunk * NSTRIP;

        const float* plane = xb + c * HW;
        const int gxu  = bx0 - HX + strip * 4;
        const bool edge = (gxu < 0) || (gxu > Wd - 4);
        const int cx0 = clampi(gxu + 0, 0, Wd - 1);
        const int cx1 = clampi(gxu + 1, 0, Wd - 1);
        const int cx2 = clampi(gxu + 2, 0, Wd - 1);
        const int cx3 = clampi(gxu + 3, 0, Wd - 1);
        const int ybase = by0 + chunk * CHUNK;
        const int sw0 = swz(2 * strip) * 4;       // float offset of word 0
        const int sw1 = swz(2 * strip + 1) * 4;   // float offset of word 1

        const uint64_t Wm0 = pk(wm0, wm0), Wm1 = pk(wm1, wm1);
        const uint64_t Wp0 = pk(wp0, wp0), Wp1 = pk(wp1, wp1);

        auto ldrow = [&](int yy) -> P2 {
            const int yo = clampi(yy, 0, Hd - 1) * Wd;
            float4 v;
            if (!edge) {
                v = __ldg((const float4*)(plane + yo + gxu));
            } else {
                v.x = __ldg(plane + yo + cx0);
                v.y = __ldg(plane + yo + cx1);
                v.z = __ldg(plane + yo + cx2);
                v.w = __ldg(plane + yo + cx3);
            }
            P2 p; p.lo = pk(v.x, v.y); p.hi = pk(v.z, v.w);
            return p;
        };

        constexpr int WIN = 2 * JP + 3;
        P2 win[WIN];
        #pragma unroll
        for (int r = -JP - 1; r <= JP; ++r)
            win[r + JP + 1] = ldrow(ybase + r);

        float* rowbase = smI + (c * TY + chunk * CHUNK) * ROWF;

        #pragma unroll
        for (int j = 0; j < CHUNK; ++j) {
            win[(j + 2 * JP + 2) % WIN] = ldrow(ybase + j + JP + 1);

            P2 m0 = win[(j)              % WIN];
            P2 m1 = win[(j + 1)          % WIN];
            P2 ce = win[(j + JP + 1)     % WIN];
            P2 p0 = win[(j + 2 * JP + 1) % WIN];
            P2 p1 = win[(j + 2 * JP + 2) % WIN];

            uint64_t mpl = fma2(Wm1, m1.lo, mul2(Wm0, m0.lo));
            uint64_t mph = fma2(Wm1, m1.hi, mul2(Wm0, m0.hi));
            uint64_t ppl = fma2(Wp1, p1.lo, mul2(Wp0, p0.lo));
            uint64_t pph = fma2(Wp1, p1.hi, mul2(Wp0, p0.hi));
            uint64_t vsl = add2(ce.lo, add2(mpl, ppl));   // (S0,S1)
            uint64_t vsh = add2(ce.hi, add2(mph, pph));   // (S2,S3)
            uint64_t vgl = fma2(mpl, NEG1_2, ppl);        // (G0,G1)
            uint64_t vgh = fma2(mph, NEG1_2, pph);        // (G2,G3)

            float s0, s1, s2, s3, g0, g1, g2, g3;
            upk(vsl, s0, s1); upk(vsh, s2, s3);
            upk(vgl, g0, g1); upk(vgh, g2, g3);
            float* row = rowbase + j * ROWF;
            *(float4*)(row + sw0) = make_float4(s0, g0, s1, g1);
            *(float4*)(row + sw1) = make_float4(s2, g2, s3, g3);
        }
    }
    __syncthreads();

    // ---------------- Phase 2: packed dual stencil + quadratics ----------------
    const int cg = tid & 31;         // col group 0..31 (4 px each)
    const int tyh = tid >> 5;        // 0..7
    const int xl  = cg * 4;
    const int r0  = tyh * 2;

    int fo[6];
    #pragma unroll
    for (int j = 0; j < 6; ++j) fo[j] = swz(2 * cg + j) * 4;

    constexpr int dM = 3 - JP;
    constexpr int dP = 4 + JP;

    // Packed weights (d_k, s_k): lane0 = derivative (su), lane1 = smooth (sv).
    const uint64_t WdM  = pk(-wm0, wm0);
    const uint64_t WdM1 = pk(-wm1, wm1);
    const uint64_t Wc   = pk(0.f, 1.f);
    const uint64_t WdP  = pk(wp0, wp0);
    const uint64_t WdP1 = pk(wp1, wp1);

    uint64_t qAB[2][4];
    float    qC[2][4];
    #pragma unroll
    for (int rr = 0; rr < 2; ++rr)
        #pragma unroll
        for (int i = 0; i < 4; ++i) { qAB[rr][i] = 0; qC[rr][i] = 0.f; }

    #pragma unroll
    for (int c = 0; c < 3; ++c) {
        #pragma unroll
        for (int rr = 0; rr < 2; ++rr) {
            const float* row = smI + (c * TY + r0 + rr) * ROWF;
            ulonglong2 u0 = *(const ulonglong2*)(row + fo[0]);
            ulonglong2 u1 = *(const ulonglong2*)(row + fo[1]);
            ulonglong2 u2 = *(const ulonglong2*)(row + fo[2]);
            ulonglong2 u3 = *(const ulonglong2*)(row + fo[3]);
            ulonglong2 u4 = *(const ulonglong2*)(row + fo[4]);
            ulonglong2 u5 = *(const ulonglong2*)(row + fo[5]);
            uint64_t pw[12] = {u0.x, u0.y, u1.x, u1.y, u2.x, u2.y,
                               u3.x, u3.y, u4.x, u4.y, u5.x, u5.y};
            #pragma unroll
            for (int i = 0; i < 4; ++i) {
                uint64_t acc = mul2(WdM, pw[i + dM]);
                acc = fma2(WdM1, pw[i + dM + 1], acc);
                acc = fma2(Wc,   pw[i + 4],      acc);
                acc = fma2(WdP,  pw[i + dP],     acc);
                acc = fma2(WdP1, pw[i + dP + 1], acc);
                if (c == 0) acc = mul2(acc, C100_2);
                qAB[rr][i] = fma2(acc, acc, qAB[rr][i]);
                float su_s, sv_s;
                upk(acc, su_s, sv_s);
                qC[rr][i] = fmaf(su_s, sv_s, qC[rr][i]);
            }
        }
    }

    // ---------------- Output ----------------
    float* out0 = out + (b * 3 + 0) * HW;
    float* out1 = out + (b * 3 + 1) * HW;
    float* out2 = out + (b * 3 + 2) * HW;
    const int gxg = bx0 + xl;

    #pragma unroll
    for (int rr = 0; rr < 2; ++rr) {
        const int gy = by0 + r0 + rr;
        const int o  = gy * Wd + gxg;
        float A[4], Bv[4];
        #pragma unroll
        for (int i = 0; i < 4; ++i) upk(qAB[rr][i], A[i], Bv[i]);

        if (gxg >= 4 && gy > JP) {
            *(float4*)(out0 + o) = make_float4(A[0], A[1], A[2], A[3]);
            *(float4*)(out1 + o) = make_float4(Bv[0], Bv[1], Bv[2], Bv[3]);
            *(float4*)(out2 + o) = make_float4(qC[rr][0], qC[rr][1], qC[rr][2], qC[rr][3]);
        } else {
            #pragma unroll
            for (int i = 0; i < 4; ++i) {
                int gx = gxg + i;
                float a = A[i], bq = Bv[i], cq = qC[rr][i];
                if (gx <= JP || gy <= JP) {
                    exact_pixel(xb, s, gx, gy, a, bq, cq);
                }
                out0[o + i] = a;
                out1[o + i] = bq;
                out2[o + i] = cq;
            }
        }
    }
}

__global__ __launch_bounds__(NTH, 3)
void st14_kernel(const float* __restrict__ x, const float* __restrict__ sigma,
                 float* __restrict__ out) {
    extern __shared__ float sm[];

    const int b   = blockIdx.z;
    const int bx0 = blockIdx.x * TX;
    const int by0 = blockIdx.y * TY;
    const int tid = threadIdx.x;

    const float s = __ldg(&sigma[b]);
    const int jp = clampi((int)floorf(s), 0, 2);
    const float* xb = x + b * 3 * HW;

    if (jp == 0)      run_tile<0>(xb, s, sm, out, b, bx0, by0, tid);
    else if (jp == 1) run_tile<1>(xb, s, sm, out, b, bx0, by0, tid);
    else              run_tile<2>(xb, s, sm, out, b, bx0, by0, tid);
}

extern "C" void kernel_launch(void* const* d_in, const int* in_sizes, int n_in,
                              void* d_out, int out_size) {
    const float* x     = (const float*)d_in[0];
    const float* sigma = (const float*)d_in[1];
    float* out = (float*)d_out;
    int B = in_sizes[1];

    static_assert(SMEM_BYTES == 52224, "smem size");
    cudaFuncSetAttribute(st14_kernel, cudaFuncAttributeMaxDynamicSharedMemorySize, SMEM_BYTES);

    dim3 grid(Wd / TX, Hd / TY, B);
    st14_kernel<<<grid, NTH, SMEM_BYTES>>>(x, sigma, out);
}